// round 2
// baseline (speedup 1.0000x reference)
#include <cuda_runtime.h>
#include <cstdint>
#include <cstdio>

#define TT   200
#define BB   4096
#define OBS  64
#define HID  128
#define LAT  3
#define NENC 50
#define DH   100

// ---------------- scratch (static device allocations; no cudaMalloc) -------
__device__ float g_hA[BB * HID];
__device__ float g_hB[BB * HID];
__device__ float g_g[BB * 512];        // packed GRU pre-activations per step
__device__ float g_wcat[192 * 512];    // packed GRU weight matrix
__device__ float g_z0[BB * LAT];
__device__ float g_mean[BB * LAT];
__device__ float g_logvar[BB * LAT];
__device__ float g_traj[(size_t)TT * BB * LAT];

// ---------------------------------------------------------------------------
// Pack W into [192][512]:
//  cols [0,256): r,z rows (j=c), K=192 (x then h)
//  cols [256,384): i_n rows (j=c in 256..383), K<64 only
//  cols [384,512): h_n rows (j=c-128 in 256..383), K>=64 only
// ---------------------------------------------------------------------------
__global__ void prep_wcat(const float* __restrict__ Wih,
                          const float* __restrict__ Whh,
                          float* __restrict__ wcat) {
    int i = blockIdx.x * blockDim.x + threadIdx.x;
    if (i >= 192 * 512) return;
    int k = i >> 9;
    int c = i & 511;
    float v;
    if (c < 256)      v = (k < 64) ? Wih[c * 64 + k] : Whh[c * 128 + (k - 64)];
    else if (c < 384) v = (k < 64) ? Wih[c * 64 + k] : 0.f;
    else {
        int j = c - 128;
        v = (k < 64) ? 0.f : Whh[j * 128 + (k - 64)];
    }
    wcat[i] = v;
}

// ---------------------------------------------------------------------------
// SGEMM: g[4096,512] = [x_t | h][4096,192] @ wcat[192,512]
// BM=64 BN=64 BK=16, 128 threads, 4x8 microtile
// ---------------------------------------------------------------------------
__global__ __launch_bounds__(128) void gru_gemm(const float* __restrict__ xt,
                                                const float* __restrict__ h,
                                                const float* __restrict__ wcat,
                                                float* __restrict__ g) {
    __shared__ float As[16][68];  // [k][row], row stride 68 floats (272B = 16*17, 16B aligned)
    __shared__ float Bs[16][68];  // [k][col]
    int tid = threadIdx.x;
    int bm = blockIdx.x, bn = blockIdx.y;
    int tm = tid & 15, tn = tid >> 4;

    float acc[4][8];
#pragma unroll
    for (int i = 0; i < 4; i++)
#pragma unroll
        for (int j = 0; j < 8; j++) acc[i][j] = 0.f;

    int a_r  = tid >> 1;
    int a_k0 = (tid & 1) * 8;
    int b_k  = tid >> 3;
    int b_c0 = (tid & 7) * 8;
    int arow = bm * 64 + a_r;

    for (int kt = 0; kt < 12; kt++) {
        int kg0 = kt * 16 + a_k0;
        float4 av0, av1;
        if (kg0 < 64) {
            av0 = *(const float4*)(xt + (size_t)arow * 64 + kg0);
            av1 = *(const float4*)(xt + (size_t)arow * 64 + kg0 + 4);
        } else {
            av0 = *(const float4*)(h + (size_t)arow * 128 + (kg0 - 64));
            av1 = *(const float4*)(h + (size_t)arow * 128 + (kg0 - 64) + 4);
        }
        As[a_k0 + 0][a_r] = av0.x; As[a_k0 + 1][a_r] = av0.y;
        As[a_k0 + 2][a_r] = av0.z; As[a_k0 + 3][a_r] = av0.w;
        As[a_k0 + 4][a_r] = av1.x; As[a_k0 + 5][a_r] = av1.y;
        As[a_k0 + 6][a_r] = av1.z; As[a_k0 + 7][a_r] = av1.w;

        const float* bp = wcat + (size_t)(kt * 16 + b_k) * 512 + bn * 64 + b_c0;
        *(float4*)&Bs[b_k][b_c0]     = *(const float4*)bp;
        *(float4*)&Bs[b_k][b_c0 + 4] = *(const float4*)(bp + 4);
        __syncthreads();

#pragma unroll
        for (int kk = 0; kk < 16; kk++) {
            float4 a  = *(const float4*)&As[kk][tm * 4];
            float4 b0 = *(const float4*)&Bs[kk][tn * 8];
            float4 b1 = *(const float4*)&Bs[kk][tn * 8 + 4];
            float ar[4] = {a.x, a.y, a.z, a.w};
            float br[8] = {b0.x, b0.y, b0.z, b0.w, b1.x, b1.y, b1.z, b1.w};
#pragma unroll
            for (int i = 0; i < 4; i++)
#pragma unroll
                for (int j = 0; j < 8; j++)
                    acc[i][j] = fmaf(ar[i], br[j], acc[i][j]);
        }
        __syncthreads();
    }
#pragma unroll
    for (int i = 0; i < 4; i++) {
        float* gp = g + (size_t)(bm * 64 + tm * 4 + i) * 512 + bn * 64 + tn * 8;
        *(float4*)gp       = make_float4(acc[i][0], acc[i][1], acc[i][2], acc[i][3]);
        *(float4*)(gp + 4) = make_float4(acc[i][4], acc[i][5], acc[i][6], acc[i][7]);
    }
}

// ---------------------------------------------------------------------------
// GRU gates: h_new = (1-z)*tanh(i_n + r*h_n) + z*h
// ---------------------------------------------------------------------------
__global__ void gru_gate(const float* __restrict__ g,
                         const float* __restrict__ bih,
                         const float* __restrict__ bhh,
                         const float* __restrict__ hold,
                         float* __restrict__ hnew) {
    int i = blockIdx.x * blockDim.x + threadIdx.x;
    if (i >= BB * HID) return;
    int b = i >> 7, j = i & 127;
    const float* gb = g + (size_t)b * 512;
    float pr  = gb[j]       + bih[j]       + bhh[j];
    float pz  = gb[128 + j] + bih[128 + j] + bhh[128 + j];
    float in_ = gb[256 + j] + bih[256 + j];
    float hn_ = gb[384 + j] + bhh[256 + j];
    float r  = 1.f / (1.f + expf(-pr));
    float zg = 1.f / (1.f + expf(-pz));
    float n  = tanhf(fmaf(r, hn_, in_));
    hnew[i] = (1.f - zg) * n + zg * hold[i];
}

// ---------------------------------------------------------------------------
// z0_mean / z0_logvar / z0  (warp per batch row)
// ---------------------------------------------------------------------------
__global__ __launch_bounds__(128) void latent_head(const float* __restrict__ h,
                                                   const float* __restrict__ mW,
                                                   const float* __restrict__ mb,
                                                   const float* __restrict__ lW,
                                                   const float* __restrict__ lb,
                                                   const float* __restrict__ eps,
                                                   float* __restrict__ omean,
                                                   float* __restrict__ ologv,
                                                   float* __restrict__ z0) {
    int tid = threadIdx.x, lane = tid & 31, wrp = tid >> 5;
    int b = blockIdx.x * 4 + wrp;
    if (b >= BB) return;
    float hm[4];
#pragma unroll
    for (int m = 0; m < 4; m++) hm[m] = h[(size_t)b * 128 + lane + 32 * m];
#pragma unroll
    for (int c = 0; c < 3; c++) {
        float pm = 0.f, pl = 0.f;
#pragma unroll
        for (int m = 0; m < 4; m++) {
            int k = lane + 32 * m;
            pm = fmaf(hm[m], mW[c * 128 + k], pm);
            pl = fmaf(hm[m], lW[c * 128 + k], pl);
        }
#pragma unroll
        for (int off = 16; off > 0; off >>= 1) {
            pm += __shfl_xor_sync(0xffffffffu, pm, off);
            pl += __shfl_xor_sync(0xffffffffu, pl, off);
        }
        if (lane == 0) {
            float mean = pm + mb[c];
            float lv   = pl + lb[c];
            float z    = mean + eps[b * 3 + c] * expf(0.5f * lv);
            omean[b * 3 + c] = mean;
            ologv[b * 3 + c] = lv;
            z0[b * 3 + c]    = z;
        }
    }
}

// ---------------------------------------------------------------------------
// ODE: RK4 (h=0.04, 50 steps) + cubic Hermite dense output at 0.01 grid.
// One warp integrates 4 batch elements (state replicated across lanes).
// Lane handles hidden rows j = lane + 32m.
// ---------------------------------------------------------------------------
__device__ __forceinline__ void dyn_eval(const float (&zs)[4][3], float (&f)[4][3],
                                         const int (&jr)[4], const float (&w1r)[4][3],
                                         const float (&b1r)[4], const float (&b2r)[4],
                                         const float (&w3r)[3][4], const float (&b3r)[3],
                                         const float* __restrict__ W2s,
                                         float* __restrict__ mysh, int lane) {
    __syncwarp();
    // layer 1: h1 = tanh(W1 z + b1) -> shared [k][e]
#pragma unroll
    for (int m = 0; m < 4; m++) {
        if (lane + 32 * m < 100) {
#pragma unroll
            for (int e = 0; e < 4; e++) {
                float v = fmaf(w1r[m][0], zs[e][0],
                          fmaf(w1r[m][1], zs[e][1],
                          fmaf(w1r[m][2], zs[e][2], b1r[m])));
                mysh[jr[m] * 4 + e] = tanhf(v);
            }
        }
    }
    __syncwarp();
    // layer 2
    float acc[4][4];
#pragma unroll
    for (int m = 0; m < 4; m++)
#pragma unroll
        for (int e = 0; e < 4; e++) acc[m][e] = b2r[m];
#pragma unroll 2
    for (int k = 0; k < 100; k++) {
        float4 hv = *(const float4*)(mysh + 4 * k);
#pragma unroll
        for (int m = 0; m < 4; m++) {
            float w = W2s[jr[m] * 101 + k];
            acc[m][0] = fmaf(w, hv.x, acc[m][0]);
            acc[m][1] = fmaf(w, hv.y, acc[m][1]);
            acc[m][2] = fmaf(w, hv.z, acc[m][2]);
            acc[m][3] = fmaf(w, hv.w, acc[m][3]);
        }
    }
    // layer 3 partials
    float p[3][4];
#pragma unroll
    for (int c = 0; c < 3; c++)
#pragma unroll
        for (int e = 0; e < 4; e++) p[c][e] = 0.f;
#pragma unroll
    for (int m = 0; m < 4; m++) {
        float h2e[4];
#pragma unroll
        for (int e = 0; e < 4; e++) h2e[e] = tanhf(acc[m][e]);
#pragma unroll
        for (int c = 0; c < 3; c++) {
            float w = w3r[c][m];  // zero for invalid rows
#pragma unroll
            for (int e = 0; e < 4; e++) p[c][e] = fmaf(w, h2e[e], p[c][e]);
        }
    }
#pragma unroll
    for (int c = 0; c < 3; c++)
#pragma unroll
        for (int e = 0; e < 4; e++) {
            float v = p[c][e];
            v += __shfl_xor_sync(0xffffffffu, v, 16);
            v += __shfl_xor_sync(0xffffffffu, v, 8);
            v += __shfl_xor_sync(0xffffffffu, v, 4);
            v += __shfl_xor_sync(0xffffffffu, v, 2);
            v += __shfl_xor_sync(0xffffffffu, v, 1);
            f[e][c] = v + b3r[c];
        }
}

__global__ __launch_bounds__(128) void ode_kernel(const float* __restrict__ z0in,
                                                  const float* __restrict__ W1,
                                                  const float* __restrict__ b1,
                                                  const float* __restrict__ W2,
                                                  const float* __restrict__ b2,
                                                  const float* __restrict__ W3,
                                                  const float* __restrict__ b3,
                                                  float* __restrict__ traj) {
    __shared__ float W2s[100 * 101];
    __shared__ float sh1[4][400];
    int tid = threadIdx.x, lane = tid & 31, wrp = tid >> 5;

    for (int i = tid; i < 10000; i += 128) {
        int r = i / 100, c = i - r * 100;
        W2s[r * 101 + c] = W2[i];
    }
    int jr[4];
    float w1r[4][3], b1r[4], b2r[4], w3r[3][4];
#pragma unroll
    for (int m = 0; m < 4; m++) {
        int j = lane + 32 * m;
        bool v = (j < 100);
        jr[m] = v ? j : 99;
        w1r[m][0] = v ? W1[j * 3 + 0] : 0.f;
        w1r[m][1] = v ? W1[j * 3 + 1] : 0.f;
        w1r[m][2] = v ? W1[j * 3 + 2] : 0.f;
        b1r[m] = v ? b1[j] : 0.f;
        b2r[m] = v ? b2[j] : 0.f;
#pragma unroll
        for (int c = 0; c < 3; c++) w3r[c][m] = v ? W3[c * 100 + j] : 0.f;
    }
    float b3r[3] = {b3[0], b3[1], b3[2]};
    __syncthreads();

    int e0 = (blockIdx.x * 4 + wrp) * 4;
    float* mysh = sh1[wrp];

    float z[4][3];
#pragma unroll
    for (int e = 0; e < 4; e++)
#pragma unroll
        for (int c = 0; c < 3; c++) z[e][c] = z0in[(size_t)(e0 + e) * 3 + c];

    float f0[4][3];
    dyn_eval(z, f0, jr, w1r, b1r, b2r, w3r, b3r, W2s, mysh, lane);

    const float H = 0.04f, H2 = 0.02f, H6 = 0.04f / 6.f;

    for (int m = 0; m < 50; m++) {
        float zs[4][3], kx[4][3], sum[4][3], z1[4][3], f1[4][3];
#pragma unroll
        for (int e = 0; e < 4; e++)
#pragma unroll
            for (int c = 0; c < 3; c++) {
                sum[e][c] = f0[e][c];
                zs[e][c]  = fmaf(H2, f0[e][c], z[e][c]);
            }
        dyn_eval(zs, kx, jr, w1r, b1r, b2r, w3r, b3r, W2s, mysh, lane);   // k2
#pragma unroll
        for (int e = 0; e < 4; e++)
#pragma unroll
            for (int c = 0; c < 3; c++) {
                sum[e][c] = fmaf(2.f, kx[e][c], sum[e][c]);
                zs[e][c]  = fmaf(H2, kx[e][c], z[e][c]);
            }
        dyn_eval(zs, kx, jr, w1r, b1r, b2r, w3r, b3r, W2s, mysh, lane);   // k3
#pragma unroll
        for (int e = 0; e < 4; e++)
#pragma unroll
            for (int c = 0; c < 3; c++) {
                sum[e][c] = fmaf(2.f, kx[e][c], sum[e][c]);
                zs[e][c]  = fmaf(H, kx[e][c], z[e][c]);
            }
        dyn_eval(zs, kx, jr, w1r, b1r, b2r, w3r, b3r, W2s, mysh, lane);   // k4
#pragma unroll
        for (int e = 0; e < 4; e++)
#pragma unroll
            for (int c = 0; c < 3; c++) {
                sum[e][c] += kx[e][c];
                z1[e][c] = fmaf(H6, sum[e][c], z[e][c]);
            }
        dyn_eval(z1, f1, jr, w1r, b1r, b2r, w3r, b3r, W2s, mysh, lane);   // f at t1

        // stage outputs: s=0 -> z, s=1..3 -> Hermite
        __syncwarp();
        if (lane == 0) {
#pragma unroll
            for (int e = 0; e < 4; e++)
#pragma unroll
                for (int c = 0; c < 3; c++) mysh[e * 3 + c] = z[e][c];
#pragma unroll
            for (int si = 1; si < 4; si++) {
                float s  = 0.25f * si;
                float s2 = s * s, s3 = s2 * s;
                float h00 = 2.f * s3 - 3.f * s2 + 1.f;
                float h10 = s3 - 2.f * s2 + s;
                float h01 = -2.f * s3 + 3.f * s2;
                float h11 = s3 - s2;
#pragma unroll
                for (int e = 0; e < 4; e++)
#pragma unroll
                    for (int c = 0; c < 3; c++) {
                        float pv = h00 * z[e][c] + h10 * H * f0[e][c]
                                 + h01 * z1[e][c] + h11 * H * f1[e][c];
                        mysh[si * 12 + e * 3 + c] = pv;
                    }
            }
        }
        __syncwarp();
#pragma unroll
        for (int si = 0; si < 4; si++) {
            if (lane < 12)
                traj[((size_t)(4 * m + si) * BB + e0) * 3 + lane] = mysh[si * 12 + lane];
        }
        __syncwarp();
#pragma unroll
        for (int e = 0; e < 4; e++)
#pragma unroll
            for (int c = 0; c < 3; c++) { z[e][c] = z1[e][c]; f0[e][c] = f1[e][c]; }
    }
}

// ---------------------------------------------------------------------------
// Decoder: recon = relu(traj@W1^T + b1)@W2^T + b2, warp per row, looped.
// ---------------------------------------------------------------------------
__global__ __launch_bounds__(256) void decoder(const float* __restrict__ traj,
                                               const float* __restrict__ W1,
                                               const float* __restrict__ b1,
                                               const float* __restrict__ W2,
                                               const float* __restrict__ b2,
                                               float* __restrict__ recon) {
    __shared__ float4 W1s[64];
    __shared__ float W2Ts[64][64];
    __shared__ float b2s[64];
    int tid = threadIdx.x, lane = tid & 31, wrp = tid >> 5;
    if (tid < 64) {
        W1s[tid] = make_float4(W1[tid * 3], W1[tid * 3 + 1], W1[tid * 3 + 2], b1[tid]);
        b2s[tid] = b2[tid];
    }
    for (int i = tid; i < 4096; i += 256) {
        int c = i >> 6, j = i & 63;
        W2Ts[j][c] = W2[i];
    }
    __syncthreads();

    int gw = blockIdx.x * 8 + wrp;
    for (int row = gw; row < TT * BB; row += 16384) {
        const float* zp = traj + (size_t)row * 3;
        float z0v = zp[0], z1v = zp[1], z2v = zp[2];
        float hh[2];
#pragma unroll
        for (int s = 0; s < 2; s++) {
            float4 w = W1s[lane + 32 * s];
            float v = fmaf(w.x, z0v, fmaf(w.y, z1v, fmaf(w.z, z2v, w.w)));
            hh[s] = v > 0.f ? v : 0.f;
        }
        float o0 = b2s[lane], o1 = b2s[lane + 32];
#pragma unroll
        for (int j = 0; j < 64; j++) {
            float hj = __shfl_sync(0xffffffffu, hh[j >> 5], j & 31);
            o0 = fmaf(W2Ts[j][lane], hj, o0);
            o1 = fmaf(W2Ts[j][lane + 32], hj, o1);
        }
        float* rp = recon + (size_t)row * 64;
        rp[lane]      = o0;
        rp[lane + 32] = o1;
    }
}

// ---------------------------------------------------------------------------
extern "C" void kernel_launch(void* const* d_in, const int* in_sizes, int n_in,
                              void* d_out, int out_size) {
    const float* obs   = (const float*)d_in[0];
    const float* eps   = (const float*)d_in[1];
    const float* Wih   = (const float*)d_in[2];
    const float* Whh   = (const float*)d_in[3];
    const float* bih   = (const float*)d_in[4];
    const float* bhh   = (const float*)d_in[5];
    const float* meanW = (const float*)d_in[6];
    const float* meanb = (const float*)d_in[7];
    const float* logW  = (const float*)d_in[8];
    const float* logb  = (const float*)d_in[9];
    const float* dW1   = (const float*)d_in[10];
    const float* db1   = (const float*)d_in[11];
    const float* dW2   = (const float*)d_in[12];
    const float* db2   = (const float*)d_in[13];
    const float* dW3   = (const float*)d_in[14];
    const float* db3   = (const float*)d_in[15];
    const float* eW1   = (const float*)d_in[16];
    const float* eb1   = (const float*)d_in[17];
    const float* eW2   = (const float*)d_in[18];
    const float* eb2   = (const float*)d_in[19];
    // d_in[20] = time_steps (uniform 0.01 grid by construction; unused)
    float* out = (float*)d_out;

    float *hA, *hB, *gbuf, *wcat, *z0s, *meanbuf, *logbuf, *traj;
    cudaGetSymbolAddress((void**)&hA, g_hA);
    cudaGetSymbolAddress((void**)&hB, g_hB);
    cudaGetSymbolAddress((void**)&gbuf, g_g);
    cudaGetSymbolAddress((void**)&wcat, g_wcat);
    cudaGetSymbolAddress((void**)&z0s, g_z0);
    cudaGetSymbolAddress((void**)&meanbuf, g_mean);
    cudaGetSymbolAddress((void**)&logbuf, g_logvar);
    cudaGetSymbolAddress((void**)&traj, g_traj);

    cudaMemsetAsync(hA, 0, (size_t)BB * HID * sizeof(float));
    prep_wcat<<<(192 * 512 + 255) / 256, 256>>>(Wih, Whh, wcat);

    float* hc = hA;
    float* hn = hB;
    for (int t = 0; t < NENC; t++) {
        gru_gemm<<<dim3(BB / 64, 512 / 64), 128>>>(obs + (size_t)t * BB * OBS, hc, wcat, gbuf);
        gru_gate<<<(BB * HID + 255) / 256, 256>>>(gbuf, bih, bhh, hc, hn);
        float* tmp = hc; hc = hn; hn = tmp;
    }

    latent_head<<<BB / 4, 128>>>(hc, meanW, meanb, logW, logb, eps, meanbuf, logbuf, z0s);
    ode_kernel<<<256, 128>>>(z0s, dW1, db1, dW2, db2, dW3, db3, traj);
    decoder<<<2048, 256>>>(traj, eW1, eb1, eW2, eb2, out);

    // pack remaining outputs: recon | z0_mean | z0_logvar | traj
    const size_t OFF_MEAN = (size_t)TT * BB * OBS;            // 52,428,800
    const size_t NLAT = (size_t)BB * LAT;
    if ((size_t)out_size >= OFF_MEAN + 2 * NLAT + (size_t)TT * BB * LAT) {
        cudaMemcpyAsync(out + OFF_MEAN, meanbuf, NLAT * sizeof(float),
                        cudaMemcpyDeviceToDevice);
        cudaMemcpyAsync(out + OFF_MEAN + NLAT, logbuf, NLAT * sizeof(float),
                        cudaMemcpyDeviceToDevice);
        cudaMemcpyAsync(out + OFF_MEAN + 2 * NLAT, traj,
                        (size_t)TT * BB * LAT * sizeof(float),
                        cudaMemcpyDeviceToDevice);
    }
}

// round 5
// speedup vs baseline: 2.1522x; 2.1522x over previous
#include <cuda_runtime.h>
#include <cstdint>

#define TT   200
#define BB   4096
#define OBS  64
#define HID  128
#define LAT  3
#define NENC 50

// ---------------- static scratch ----------------
__device__ float g_gix[(size_t)NENC * BB * 384];   // precomputed x-gates (+bias)
__device__ float g_hlast[BB * HID];
__device__ float g_z0[BB * LAT];

__device__ __forceinline__ float fsig(float x) {
    return __fdividef(1.f, 1.f + __expf(-x));
}
__device__ __forceinline__ float ftanh(float x) {
    return 1.f - __fdividef(2.f, __expf(2.f * x) + 1.f);
}

// ---------------------------------------------------------------------------
// X-projection GEMM: gix[204800,384] = obs[:50][204800,64] @ Wih^T + bias
// bias(c) = bih[c] + (c<256 ? bhh[c] : 0)
// BM=128 BN=128 BK=16, 256 threads, 8x8 microtile (split 4+4 at +64)
// ---------------------------------------------------------------------------
__global__ __launch_bounds__(256) void xgemm(const float* __restrict__ obs,
                                             const float* __restrict__ Wih,
                                             const float* __restrict__ bih,
                                             const float* __restrict__ bhh,
                                             float* __restrict__ gix) {
    __shared__ __align__(16) float As[16 * 132];
    __shared__ __align__(16) float Bs[16 * 132];
    int tid = threadIdx.x;
    int m0 = blockIdx.x * 128;
    int n0 = blockIdx.y * 128;
    int tm = tid >> 4, tn = tid & 15;

    float acc[8][8];
#pragma unroll
    for (int i = 0; i < 8; i++)
#pragma unroll
        for (int j = 0; j < 8; j++) acc[i][j] = 0.f;

    for (int kt = 0; kt < 4; kt++) {
#pragma unroll
        for (int p = 0; p < 2; p++) {
            int idx = tid + p * 256;
            int row = idx >> 2, kq = idx & 3;
            float4 v = *(const float4*)(obs + (size_t)(m0 + row) * 64 + kt * 16 + kq * 4);
            As[(kq * 4 + 0) * 132 + row] = v.x;
            As[(kq * 4 + 1) * 132 + row] = v.y;
            As[(kq * 4 + 2) * 132 + row] = v.z;
            As[(kq * 4 + 3) * 132 + row] = v.w;
        }
#pragma unroll
        for (int p = 0; p < 8; p++) {
            int i = tid + p * 256;
            int k = i & 15, c = i >> 4;
            Bs[k * 132 + c] = Wih[(size_t)(n0 + c) * 64 + kt * 16 + k];
        }
        __syncthreads();
#pragma unroll
        for (int kk = 0; kk < 16; kk++) {
            float4 a0 = *(const float4*)&As[kk * 132 + tm * 4];
            float4 a1 = *(const float4*)&As[kk * 132 + tm * 4 + 64];
            float4 b0 = *(const float4*)&Bs[kk * 132 + tn * 4];
            float4 b1 = *(const float4*)&Bs[kk * 132 + tn * 4 + 64];
            float ar[8] = {a0.x, a0.y, a0.z, a0.w, a1.x, a1.y, a1.z, a1.w};
            float br[8] = {b0.x, b0.y, b0.z, b0.w, b1.x, b1.y, b1.z, b1.w};
#pragma unroll
            for (int i = 0; i < 8; i++)
#pragma unroll
                for (int j = 0; j < 8; j++)
                    acc[i][j] = fmaf(ar[i], br[j], acc[i][j]);
        }
        __syncthreads();
    }
#pragma unroll
    for (int ih = 0; ih < 2; ih++)
#pragma unroll
        for (int i = 0; i < 4; i++) {
            int row = m0 + tm * 4 + i + ih * 64;
#pragma unroll
            for (int jh = 0; jh < 2; jh++) {
                int cb = n0 + tn * 4 + jh * 64;
                float4 o;
                float bx[4];
#pragma unroll
                for (int j = 0; j < 4; j++) {
                    int c = cb + j;
                    bx[j] = bih[c] + (c < 256 ? bhh[c] : 0.f);
                }
                o.x = acc[ih * 4 + i][jh * 4 + 0] + bx[0];
                o.y = acc[ih * 4 + i][jh * 4 + 1] + bx[1];
                o.z = acc[ih * 4 + i][jh * 4 + 2] + bx[2];
                o.w = acc[ih * 4 + i][jh * 4 + 3] + bx[3];
                *(float4*)(gix + (size_t)row * 384 + cb) = o;
            }
        }
}

// ---------------------------------------------------------------------------
// Persistent GRU recurrence. 128 blocks x 32 batch rows, 256 threads.
// Whh (384x128, stride 132 for aligned float4 LDS) + h (32x128) in smem.
// Thread (lane,w): batch rows 4w..4w+3, hidden cols lane+32j (j=0..11 gates).
// ---------------------------------------------------------------------------
__global__ __launch_bounds__(256) void gru_rnn(const float* __restrict__ gix,
                                               const float* __restrict__ Whh,
                                               const float* __restrict__ bhh,
                                               float* __restrict__ hlast) {
    extern __shared__ float smem[];
    float* sW = smem;                 // [384][132]
    float* sH = smem + 384 * 132;     // [32][132]
    int tid = threadIdx.x, lane = tid & 31, w = tid >> 5;

    for (int i = tid * 4; i < 384 * 128; i += 1024) {
        int c = i >> 7, k = i & 127;
        float4 v = *(const float4*)(Whh + i);
        *(float4*)&sW[c * 132 + k] = v;
    }
    for (int i = tid; i < 32 * 132; i += 256) sH[i] = 0.f;
    float bhn[4];
#pragma unroll
    for (int q = 0; q < 4; q++) bhn[q] = bhh[256 + lane + 32 * q];
    __syncthreads();

    int rowg0 = blockIdx.x * 32 + 4 * w;
    const float* hrow = sH + (4 * w) * 132;
    const float* wbase = sW + lane * 132;

    for (int t = 0; t < NENC; t++) {
        // prefetch gi for this step (hidden under the GEMM)
        float gv[4][4][3];
        const float* gb = gix + ((size_t)t * BB + rowg0) * 384;
#pragma unroll
        for (int i = 0; i < 4; i++)
#pragma unroll
            for (int q = 0; q < 4; q++) {
                int u = lane + 32 * q;
                gv[i][q][0] = gb[i * 384 + u];
                gv[i][q][1] = gb[i * 384 + 128 + u];
                gv[i][q][2] = gb[i * 384 + 256 + u];
            }

        float acc[4][12];
#pragma unroll
        for (int i = 0; i < 4; i++)
#pragma unroll
            for (int j = 0; j < 12; j++) acc[i][j] = 0.f;

#pragma unroll 2
        for (int k = 0; k < 128; k += 4) {
            float4 a0 = *(const float4*)(hrow + k);
            float4 a1 = *(const float4*)(hrow + 132 + k);
            float4 a2 = *(const float4*)(hrow + 264 + k);
            float4 a3 = *(const float4*)(hrow + 396 + k);
#pragma unroll
            for (int j = 0; j < 12; j++) {
                float4 b = *(const float4*)(wbase + j * 4224 + k);
                acc[0][j] = fmaf(a0.x, b.x, fmaf(a0.y, b.y, fmaf(a0.z, b.z, fmaf(a0.w, b.w, acc[0][j]))));
                acc[1][j] = fmaf(a1.x, b.x, fmaf(a1.y, b.y, fmaf(a1.z, b.z, fmaf(a1.w, b.w, acc[1][j]))));
                acc[2][j] = fmaf(a2.x, b.x, fmaf(a2.y, b.y, fmaf(a2.z, b.z, fmaf(a2.w, b.w, acc[2][j]))));
                acc[3][j] = fmaf(a3.x, b.x, fmaf(a3.y, b.y, fmaf(a3.z, b.z, fmaf(a3.w, b.w, acc[3][j]))));
            }
        }
        __syncthreads();
#pragma unroll
        for (int i = 0; i < 4; i++)
#pragma unroll
            for (int q = 0; q < 4; q++) {
                int u = lane + 32 * q;
                float r  = fsig(gv[i][q][0] + acc[i][q]);
                float z  = fsig(gv[i][q][1] + acc[i][q + 4]);
                float n  = ftanh(gv[i][q][2] + r * (acc[i][q + 8] + bhn[q]));
                float ho = sH[(4 * w + i) * 132 + u];
                float hn = (1.f - z) * n + z * ho;
                sH[(4 * w + i) * 132 + u] = hn;
                if (t == NENC - 1)
                    hlast[(size_t)(rowg0 + i) * 128 + u] = hn;
            }
        __syncthreads();
    }
}

// ---------------------------------------------------------------------------
// z0_mean / z0_logvar / z0 (warp per batch row); writes mean/logvar to out
// ---------------------------------------------------------------------------
__global__ __launch_bounds__(128) void latent_head(const float* __restrict__ h,
                                                   const float* __restrict__ mW,
                                                   const float* __restrict__ mb,
                                                   const float* __restrict__ lW,
                                                   const float* __restrict__ lb,
                                                   const float* __restrict__ eps,
                                                   float* __restrict__ omean,
                                                   float* __restrict__ ologv,
                                                   float* __restrict__ z0) {
    int tid = threadIdx.x, lane = tid & 31, wrp = tid >> 5;
    int b = blockIdx.x * 4 + wrp;
    if (b >= BB) return;
    float hm[4];
#pragma unroll
    for (int m = 0; m < 4; m++) hm[m] = h[(size_t)b * 128 + lane + 32 * m];
#pragma unroll
    for (int c = 0; c < 3; c++) {
        float pm = 0.f, pl = 0.f;
#pragma unroll
        for (int m = 0; m < 4; m++) {
            int k = lane + 32 * m;
            pm = fmaf(hm[m], mW[c * 128 + k], pm);
            pl = fmaf(hm[m], lW[c * 128 + k], pl);
        }
#pragma unroll
        for (int off = 16; off > 0; off >>= 1) {
            pm += __shfl_xor_sync(0xffffffffu, pm, off);
            pl += __shfl_xor_sync(0xffffffffu, pl, off);
        }
        if (lane == 0) {
            float mean = pm + mb[c];
            float lv   = pl + lb[c];
            float z    = mean + eps[b * 3 + c] * __expf(0.5f * lv);
            omean[b * 3 + c] = mean;
            ologv[b * 3 + c] = lv;
            z0[b * 3 + c]    = z;
        }
    }
}

// ---------------------------------------------------------------------------
// ODE: RK4 h=0.1 (20 steps) + cubic Hermite, 10 samples/step.
// One warp integrates 4 batch elements.
// ---------------------------------------------------------------------------
__device__ __forceinline__ void dyn_eval(const float (&zs)[4][3], float (&f)[4][3],
                                         const int (&jr)[4], const float (&w1r)[4][3],
                                         const float (&b1r)[4], const float (&b2r)[4],
                                         const float (&w3r)[3][4], const float (&b3r)[3],
                                         const float* __restrict__ W2s,
                                         float* __restrict__ mysh, int lane) {
    __syncwarp();
#pragma unroll
    for (int m = 0; m < 4; m++) {
        if (lane + 32 * m < 100) {
#pragma unroll
            for (int e = 0; e < 4; e++) {
                float v = fmaf(w1r[m][0], zs[e][0],
                          fmaf(w1r[m][1], zs[e][1],
                          fmaf(w1r[m][2], zs[e][2], b1r[m])));
                mysh[jr[m] * 4 + e] = ftanh(v);
            }
        }
    }
    __syncwarp();
    float acc[4][4];
#pragma unroll
    for (int m = 0; m < 4; m++)
#pragma unroll
        for (int e = 0; e < 4; e++) acc[m][e] = b2r[m];
#pragma unroll 2
    for (int k = 0; k < 100; k++) {
        float4 hv = *(const float4*)(mysh + 4 * k);
#pragma unroll
        for (int m = 0; m < 4; m++) {
            float w = W2s[jr[m] * 101 + k];
            acc[m][0] = fmaf(w, hv.x, acc[m][0]);
            acc[m][1] = fmaf(w, hv.y, acc[m][1]);
            acc[m][2] = fmaf(w, hv.z, acc[m][2]);
            acc[m][3] = fmaf(w, hv.w, acc[m][3]);
        }
    }
    float p[3][4];
#pragma unroll
    for (int c = 0; c < 3; c++)
#pragma unroll
        for (int e = 0; e < 4; e++) p[c][e] = 0.f;
#pragma unroll
    for (int m = 0; m < 4; m++) {
        float h2e[4];
#pragma unroll
        for (int e = 0; e < 4; e++) h2e[e] = ftanh(acc[m][e]);
#pragma unroll
        for (int c = 0; c < 3; c++) {
            float w = w3r[c][m];
#pragma unroll
            for (int e = 0; e < 4; e++) p[c][e] = fmaf(w, h2e[e], p[c][e]);
        }
    }
#pragma unroll
    for (int c = 0; c < 3; c++)
#pragma unroll
        for (int e = 0; e < 4; e++) {
            float v = p[c][e];
            v += __shfl_xor_sync(0xffffffffu, v, 16);
            v += __shfl_xor_sync(0xffffffffu, v, 8);
            v += __shfl_xor_sync(0xffffffffu, v, 4);
            v += __shfl_xor_sync(0xffffffffu, v, 2);
            v += __shfl_xor_sync(0xffffffffu, v, 1);
            f[e][c] = v + b3r[c];
        }
}

__global__ __launch_bounds__(128) void ode_kernel(const float* __restrict__ z0in,
                                                  const float* __restrict__ W1,
                                                  const float* __restrict__ b1,
                                                  const float* __restrict__ W2,
                                                  const float* __restrict__ b2,
                                                  const float* __restrict__ W3,
                                                  const float* __restrict__ b3,
                                                  float* __restrict__ traj) {
    __shared__ __align__(16) float W2s[100 * 101];
    __shared__ __align__(16) float sh1[4][400];
    int tid = threadIdx.x, lane = tid & 31, wrp = tid >> 5;

    for (int i = tid; i < 10000; i += 128) {
        int r = i / 100, c = i - r * 100;
        W2s[r * 101 + c] = W2[i];
    }
    int jr[4];
    float w1r[4][3], b1r[4], b2r[4], w3r[3][4];
#pragma unroll
    for (int m = 0; m < 4; m++) {
        int j = lane + 32 * m;
        bool v = (j < 100);
        jr[m] = v ? j : 99;
        w1r[m][0] = v ? W1[j * 3 + 0] : 0.f;
        w1r[m][1] = v ? W1[j * 3 + 1] : 0.f;
        w1r[m][2] = v ? W1[j * 3 + 2] : 0.f;
        b1r[m] = v ? b1[j] : 0.f;
        b2r[m] = v ? b2[j] : 0.f;
#pragma unroll
        for (int c = 0; c < 3; c++) w3r[c][m] = v ? W3[c * 100 + j] : 0.f;
    }
    float b3r[3] = {b3[0], b3[1], b3[2]};
    __syncthreads();

    int e0 = (blockIdx.x * 4 + wrp) * 4;
    float* mysh = sh1[wrp];

    float z[4][3];
#pragma unroll
    for (int e = 0; e < 4; e++)
#pragma unroll
        for (int c = 0; c < 3; c++) z[e][c] = z0in[(size_t)(e0 + e) * 3 + c];

    float f0[4][3];
    dyn_eval(z, f0, jr, w1r, b1r, b2r, w3r, b3r, W2s, mysh, lane);

    const float H = 0.1f, H2 = 0.05f, H6 = 0.1f / 6.f;

    for (int m = 0; m < 20; m++) {
        float zs[4][3], kx[4][3], sum[4][3], z1[4][3], f1[4][3];
#pragma unroll
        for (int e = 0; e < 4; e++)
#pragma unroll
            for (int c = 0; c < 3; c++) {
                sum[e][c] = f0[e][c];
                zs[e][c]  = fmaf(H2, f0[e][c], z[e][c]);
            }
        dyn_eval(zs, kx, jr, w1r, b1r, b2r, w3r, b3r, W2s, mysh, lane);
#pragma unroll
        for (int e = 0; e < 4; e++)
#pragma unroll
            for (int c = 0; c < 3; c++) {
                sum[e][c] = fmaf(2.f, kx[e][c], sum[e][c]);
                zs[e][c]  = fmaf(H2, kx[e][c], z[e][c]);
            }
        dyn_eval(zs, kx, jr, w1r, b1r, b2r, w3r, b3r, W2s, mysh, lane);
#pragma unroll
        for (int e = 0; e < 4; e++)
#pragma unroll
            for (int c = 0; c < 3; c++) {
                sum[e][c] = fmaf(2.f, kx[e][c], sum[e][c]);
                zs[e][c]  = fmaf(H, kx[e][c], z[e][c]);
            }
        dyn_eval(zs, kx, jr, w1r, b1r, b2r, w3r, b3r, W2s, mysh, lane);
#pragma unroll
        for (int e = 0; e < 4; e++)
#pragma unroll
            for (int c = 0; c < 3; c++) {
                sum[e][c] += kx[e][c];
                z1[e][c] = fmaf(H6, sum[e][c], z[e][c]);
            }
        dyn_eval(z1, f1, jr, w1r, b1r, b2r, w3r, b3r, W2s, mysh, lane);

        // stash endpoint data for distributed Hermite evaluation
        __syncwarp();
        if (lane == 0) {
#pragma unroll
            for (int e = 0; e < 4; e++)
#pragma unroll
                for (int c = 0; c < 3; c++) {
                    mysh[e * 3 + c]      = z[e][c];
                    mysh[12 + e * 3 + c] = f0[e][c];
                    mysh[24 + e * 3 + c] = z1[e][c];
                    mysh[36 + e * 3 + c] = f1[e][c];
                }
        }
        __syncwarp();
        if (lane < 12) {
            float zz  = mysh[lane];
            float ff0 = mysh[12 + lane] * H;
            float zz1 = mysh[24 + lane];
            float ff1 = mysh[36 + lane] * H;
#pragma unroll
            for (int si = 0; si < 10; si++) {
                float s  = 0.1f * si;
                float s2 = s * s, s3 = s2 * s;
                float h00 = 2.f * s3 - 3.f * s2 + 1.f;
                float h10 = s3 - 2.f * s2 + s;
                float h01 = -2.f * s3 + 3.f * s2;
                float h11 = s3 - s2;
                float pv = h00 * zz + h10 * ff0 + h01 * zz1 + h11 * ff1;
                traj[(size_t)(10 * m + si) * BB * 3 + e0 * 3 + lane] = pv;
            }
        }
        __syncwarp();
#pragma unroll
        for (int e = 0; e < 4; e++)
#pragma unroll
            for (int c = 0; c < 3; c++) { z[e][c] = z1[e][c]; f0[e][c] = f1[e][c]; }
    }
}

// ---------------------------------------------------------------------------
// Decoder: tiled GEMM with fused relu hidden. 128 rows/block.
// ---------------------------------------------------------------------------
__global__ __launch_bounds__(256) void decoder(const float* __restrict__ traj,
                                               const float* __restrict__ W1,
                                               const float* __restrict__ b1,
                                               const float* __restrict__ W2,
                                               const float* __restrict__ b2,
                                               float* __restrict__ recon) {
    extern __shared__ float dsm[];
    float* Hs  = dsm;                    // [128][64]
    float* W2s = dsm + 8192;             // [64][65]  (layout [c][k], pad 65)
    float* zt  = dsm + 8192 + 4160;      // [128*3]
    float* W1s = zt + 384;               // [64*3]
    float* b1s = W1s + 192;              // [64]
    float* b2s = b1s + 64;               // [64]

    int tid = threadIdx.x;
    int m0 = blockIdx.x * 128;

    for (int i = tid; i < 384; i += 256) zt[i] = traj[(size_t)m0 * 3 + i];
    if (tid < 192) W1s[tid] = W1[tid];
    if (tid < 64) { b1s[tid] = b1[tid]; b2s[tid] = b2[tid]; }
    for (int i = tid; i < 4096; i += 256) {
        int c = i >> 6, k = i & 63;
        W2s[c * 65 + k] = W2[i];
    }
    __syncthreads();

    for (int idx = tid; idx < 8192; idx += 256) {
        int r = idx >> 6, c = idx & 63;
        float v = fmaf(zt[r * 3 + 0], W1s[c * 3 + 0],
                  fmaf(zt[r * 3 + 1], W1s[c * 3 + 1],
                  fmaf(zt[r * 3 + 2], W1s[c * 3 + 2], b1s[c])));
        Hs[idx] = v > 0.f ? v : 0.f;
    }
    __syncthreads();

    int tm = tid >> 4, tn = tid & 15;
    float acc[2][4][4];
#pragma unroll
    for (int h = 0; h < 2; h++)
#pragma unroll
        for (int i = 0; i < 4; i++)
#pragma unroll
            for (int j = 0; j < 4; j++) acc[h][i][j] = 0.f;

#pragma unroll 4
    for (int kk = 0; kk < 64; kk++) {
        float a[2][4], b[4];
#pragma unroll
        for (int h = 0; h < 2; h++)
#pragma unroll
            for (int i = 0; i < 4; i++)
                a[h][i] = Hs[(tm * 4 + i + 64 * h) * 64 + kk];
#pragma unroll
        for (int j = 0; j < 4; j++)
            b[j] = W2s[(tn * 4 + j) * 65 + kk];
#pragma unroll
        for (int h = 0; h < 2; h++)
#pragma unroll
            for (int i = 0; i < 4; i++)
#pragma unroll
                for (int j = 0; j < 4; j++)
                    acc[h][i][j] = fmaf(a[h][i], b[j], acc[h][i][j]);
    }
    float bb[4];
#pragma unroll
    for (int j = 0; j < 4; j++) bb[j] = b2s[tn * 4 + j];
#pragma unroll
    for (int h = 0; h < 2; h++)
#pragma unroll
        for (int i = 0; i < 4; i++) {
            int row = m0 + tm * 4 + i + 64 * h;
            float4 o = make_float4(acc[h][i][0] + bb[0], acc[h][i][1] + bb[1],
                                   acc[h][i][2] + bb[2], acc[h][i][3] + bb[3]);
            *(float4*)(recon + (size_t)row * 64 + tn * 4) = o;
        }
}

// ---------------------------------------------------------------------------
extern "C" void kernel_launch(void* const* d_in, const int* in_sizes, int n_in,
                              void* d_out, int out_size) {
    const float* obs   = (const float*)d_in[0];
    const float* eps   = (const float*)d_in[1];
    const float* Wih   = (const float*)d_in[2];
    const float* Whh   = (const float*)d_in[3];
    const float* bih   = (const float*)d_in[4];
    const float* bhh   = (const float*)d_in[5];
    const float* meanW = (const float*)d_in[6];
    const float* meanb = (const float*)d_in[7];
    const float* logW  = (const float*)d_in[8];
    const float* logb  = (const float*)d_in[9];
    const float* dW1   = (const float*)d_in[10];
    const float* db1   = (const float*)d_in[11];
    const float* dW2   = (const float*)d_in[12];
    const float* db2   = (const float*)d_in[13];
    const float* dW3   = (const float*)d_in[14];
    const float* db3   = (const float*)d_in[15];
    const float* eW1   = (const float*)d_in[16];
    const float* eb1   = (const float*)d_in[17];
    const float* eW2   = (const float*)d_in[18];
    const float* eb2   = (const float*)d_in[19];
    float* out = (float*)d_out;

    float *gix, *hlast, *z0s;
    cudaGetSymbolAddress((void**)&gix, g_gix);
    cudaGetSymbolAddress((void**)&hlast, g_hlast);
    cudaGetSymbolAddress((void**)&z0s, g_z0);

    const size_t OFF_MEAN = (size_t)TT * BB * OBS;
    const size_t NLAT = (size_t)BB * LAT;
    float* omean = out + OFF_MEAN;
    float* ologv = out + OFF_MEAN + NLAT;
    float* traj  = out + OFF_MEAN + 2 * NLAT;

    const int SMEM_RNN = (384 * 132 + 32 * 132) * 4;           // 219648 B
    const int SMEM_DEC = (8192 + 4160 + 384 + 192 + 128) * 4;  // 52224 B
    cudaFuncSetAttribute(gru_rnn, cudaFuncAttributeMaxDynamicSharedMemorySize, SMEM_RNN);
    cudaFuncSetAttribute(decoder, cudaFuncAttributeMaxDynamicSharedMemorySize, SMEM_DEC);

    xgemm<<<dim3(NENC * BB / 128, 3), 256>>>(obs, Wih, bih, bhh, gix);
    gru_rnn<<<128, 256, SMEM_RNN>>>(gix, Whh, bhh, hlast);
    latent_head<<<BB / 4, 128>>>(hlast, meanW, meanb, logW, logb, eps, omean, ologv, z0s);
    ode_kernel<<<256, 128>>>(z0s, dW1, db1, dW2, db2, dW3, db3, traj);
    decoder<<<TT * BB / 128, 256, SMEM_DEC>>>(traj, eW1, eb1, eW2, eb2, out);
}